// round 3
// baseline (speedup 1.0000x reference)
#include <cuda_runtime.h>
#include <cstddef>

#define D_MODELC 1024
#define SEQC     2048
#define BATCHC   4
#define DVC      64
#define MTOT     (BATCHC * SEQC)   // 8192

// Scratch (no allocations allowed -> __device__ globals)
__device__ float g_Q[MTOT * D_MODELC];         // 32 MB
__device__ float g_K[MTOT * D_MODELC];         // 32 MB
__device__ float g_Vp[MTOT * DVC];             // 2 MB
__device__ float g_S[BATCHC * SEQC * SEQC];    // 64 MB (scores, then attn in-place)
__device__ float g_Wvo[DVC * D_MODELC];        // 256 KB

// ---------------------------------------------------------------------------
// C[M,N] = A[M,K] @ B[N,K]^T   (both K-major / "NT"), fp32.
// 128x128 block tile, BK=8, 256 threads, 8x8 per-thread micro-tile.
// Handles N not multiple of 128 (guards). M, K assumed multiples of 128/8.
// ---------------------------------------------------------------------------
__global__ __launch_bounds__(256) void sgemm_nt(const float* __restrict__ A,
                                                const float* __restrict__ B,
                                                float* __restrict__ C,
                                                int M, int N, int K)
{
    __shared__ float As[8][128];
    __shared__ float Bs[8][128];

    const int tid  = threadIdx.x;
    const int m0   = blockIdx.y * 128;
    const int n0   = blockIdx.x * 128;
    const int lrow = tid >> 1;        // 0..127
    const int lk4  = (tid & 1) * 4;   // 0 or 4
    const int ty   = tid >> 4;        // 0..15
    const int tx   = tid & 15;        // 0..15
    const int rb   = ty * 8;
    const int cb   = tx * 8;

    const float* Arow = A + (size_t)(m0 + lrow) * K + lk4;
    const bool   bval = (n0 + lrow) < N;
    const float* Brow = B + (size_t)(n0 + lrow) * K + lk4;

    float acc[8][8];
#pragma unroll
    for (int i = 0; i < 8; i++)
#pragma unroll
        for (int j = 0; j < 8; j++) acc[i][j] = 0.f;

    for (int k0 = 0; k0 < K; k0 += 8) {
        float4 av = *(const float4*)(Arow + k0);
        float4 bv = bval ? *(const float4*)(Brow + k0) : make_float4(0.f, 0.f, 0.f, 0.f);
        As[lk4 + 0][lrow] = av.x; As[lk4 + 1][lrow] = av.y;
        As[lk4 + 2][lrow] = av.z; As[lk4 + 3][lrow] = av.w;
        Bs[lk4 + 0][lrow] = bv.x; Bs[lk4 + 1][lrow] = bv.y;
        Bs[lk4 + 2][lrow] = bv.z; Bs[lk4 + 3][lrow] = bv.w;
        __syncthreads();

#pragma unroll
        for (int k = 0; k < 8; k++) {
            float a[8], b[8];
#pragma unroll
            for (int i = 0; i < 8; i++) a[i] = As[k][rb + i];
#pragma unroll
            for (int j = 0; j < 8; j++) b[j] = Bs[k][cb + j];
#pragma unroll
            for (int i = 0; i < 8; i++)
#pragma unroll
                for (int j = 0; j < 8; j++) acc[i][j] = fmaf(a[i], b[j], acc[i][j]);
        }
        __syncthreads();
    }

#pragma unroll
    for (int i = 0; i < 8; i++) {
        const int r = m0 + rb + i;
#pragma unroll
        for (int j = 0; j < 8; j++) {
            const int c = n0 + cb + j;
            if (c < N) C[(size_t)r * N + c] = acc[i][j];
        }
    }
}

// ---------------------------------------------------------------------------
// Scores: S[b,q,k] = (sum_d Q[b,q,d]K[b,k,d]) / 32  for k<=q, else -1e30.
// Same NT-SGEMM structure; causal tile skipping (bx > by => all masked).
// ---------------------------------------------------------------------------
__global__ __launch_bounds__(256) void scores_kernel(const float* __restrict__ Qm,
                                                     const float* __restrict__ Km,
                                                     float* __restrict__ S)
{
    if (blockIdx.x > blockIdx.y) return;  // fully above diagonal -> never read

    __shared__ float As[8][128];
    __shared__ float Bs[8][128];

    const int b   = blockIdx.z;
    const float* A = Qm + (size_t)b * SEQC * D_MODELC;
    const float* B = Km + (size_t)b * SEQC * D_MODELC;
    float*       C = S  + (size_t)b * SEQC * SEQC;

    const int tid  = threadIdx.x;
    const int m0   = blockIdx.y * 128;
    const int n0   = blockIdx.x * 128;
    const int lrow = tid >> 1;
    const int lk4  = (tid & 1) * 4;
    const int ty   = tid >> 4;
    const int tx   = tid & 15;
    const int rb   = ty * 8;
    const int cb   = tx * 8;

    const float* Arow = A + (size_t)(m0 + lrow) * D_MODELC + lk4;
    const float* Brow = B + (size_t)(n0 + lrow) * D_MODELC + lk4;

    float acc[8][8];
#pragma unroll
    for (int i = 0; i < 8; i++)
#pragma unroll
        for (int j = 0; j < 8; j++) acc[i][j] = 0.f;

    for (int k0 = 0; k0 < D_MODELC; k0 += 8) {
        float4 av = *(const float4*)(Arow + k0);
        float4 bv = *(const float4*)(Brow + k0);
        As[lk4 + 0][lrow] = av.x; As[lk4 + 1][lrow] = av.y;
        As[lk4 + 2][lrow] = av.z; As[lk4 + 3][lrow] = av.w;
        Bs[lk4 + 0][lrow] = bv.x; Bs[lk4 + 1][lrow] = bv.y;
        Bs[lk4 + 2][lrow] = bv.z; Bs[lk4 + 3][lrow] = bv.w;
        __syncthreads();

#pragma unroll
        for (int k = 0; k < 8; k++) {
            float a[8], bb[8];
#pragma unroll
            for (int i = 0; i < 8; i++) a[i] = As[k][rb + i];
#pragma unroll
            for (int j = 0; j < 8; j++) bb[j] = Bs[k][cb + j];
#pragma unroll
            for (int i = 0; i < 8; i++)
#pragma unroll
                for (int j = 0; j < 8; j++) acc[i][j] = fmaf(a[i], bb[j], acc[i][j]);
        }
        __syncthreads();
    }

#pragma unroll
    for (int i = 0; i < 8; i++) {
        const int q = m0 + rb + i;
#pragma unroll
        for (int j = 0; j < 8; j++) {
            const int k = n0 + cb + j;
            C[(size_t)q * SEQC + k] = (k <= q) ? acc[i][j] * 0.03125f : -1e30f;
        }
    }
}

// ---------------------------------------------------------------------------
// Row softmax over valid prefix [0, q]; writes 0 beyond q (so ctx GEMM is
// mask-free). One block (256 threads) per row; row cached in smem.
// ---------------------------------------------------------------------------
__global__ __launch_bounds__(256) void softmax_kernel(float* __restrict__ S)
{
    __shared__ float buf[SEQC];
    __shared__ float red[256];

    const int row = blockIdx.x;            // 0..8191
    const int b   = row / SEQC;
    const int q   = row % SEQC;
    float* R = S + (size_t)b * SEQC * SEQC + (size_t)q * SEQC;
    const int n  = q + 1;
    const int tid = threadIdx.x;

    float lmax = -1e30f;
    for (int k = tid; k < n; k += 256) {
        float v = R[k];
        buf[k] = v;
        lmax = fmaxf(lmax, v);
    }
    red[tid] = lmax;
    __syncthreads();
#pragma unroll
    for (int s = 128; s > 0; s >>= 1) {
        if (tid < s) red[tid] = fmaxf(red[tid], red[tid + s]);
        __syncthreads();
    }
    const float m = red[0];
    __syncthreads();

    float lsum = 0.f;
    for (int k = tid; k < n; k += 256) {
        float e = __expf(buf[k] - m);
        buf[k] = e;
        lsum += e;
    }
    red[tid] = lsum;
    __syncthreads();
#pragma unroll
    for (int s = 128; s > 0; s >>= 1) {
        if (tid < s) red[tid] += red[tid + s];
        __syncthreads();
    }
    const float inv = 1.f / red[0];

    for (int k = tid; k < n; k += 256)       R[k] = buf[k] * inv;
    for (int k = n + tid; k < SEQC; k += 256) R[k] = 0.f;
}

// ---------------------------------------------------------------------------
// Context (fused with o-proj): O[b,q,j] = sum_k P[b,q,k] * Vp[b,k,j], j<64.
// NN layout. 128 q-rows x 64 cols per block, BK=16, 256 threads, 8x4 micro.
// Causal: skip k tiles entirely beyond this block's max q (P is 0 there).
// ---------------------------------------------------------------------------
__global__ __launch_bounds__(256) void ctx_kernel(const float* __restrict__ P,
                                                  const float* __restrict__ Vp,
                                                  float* __restrict__ O)
{
    __shared__ float Ps[16][128];
    __shared__ float Vs[16][64];

    const int b  = blockIdx.z;
    const int q0 = blockIdx.y * 128;
    const float* Pb = P  + (size_t)b * SEQC * SEQC;
    const float* Vb = Vp + (size_t)b * SEQC * DVC;
    float*       Ob = O  + (size_t)b * SEQC * DVC;

    const int tid = threadIdx.x;
    const int ty  = tid >> 4;       // 0..15
    const int tx  = tid & 15;       // 0..15
    const int rb  = ty * 8;
    const int cb  = tx * 4;

    float acc[8][4];
#pragma unroll
    for (int i = 0; i < 8; i++)
#pragma unroll
        for (int j = 0; j < 4; j++) acc[i][j] = 0.f;

    const int kmax = (q0 + 128 < SEQC) ? (q0 + 128) : SEQC;
    for (int k0 = 0; k0 < kmax; k0 += 16) {
        // P tile: 128 rows x 16 cols = 512 float4, 2 per thread (transposed store)
#pragma unroll
        for (int i = 0; i < 2; i++) {
            const int idx = tid * 2 + i;     // 0..511
            const int r   = idx >> 2;        // 0..127
            const int f4  = idx & 3;         // 0..3
            float4 v = *(const float4*)(Pb + (size_t)(q0 + r) * SEQC + k0 + f4 * 4);
            Ps[f4 * 4 + 0][r] = v.x; Ps[f4 * 4 + 1][r] = v.y;
            Ps[f4 * 4 + 2][r] = v.z; Ps[f4 * 4 + 3][r] = v.w;
        }
        // V' tile: 16 rows x 64 cols = 256 float4, 1 per thread
        {
            const int r  = tid >> 4;
            const int f4 = tid & 15;
            float4 v = *(const float4*)(Vb + (size_t)(k0 + r) * DVC + f4 * 4);
            *(float4*)&Vs[r][f4 * 4] = v;
        }
        __syncthreads();

#pragma unroll
        for (int k = 0; k < 16; k++) {
            float a[8], bb[4];
#pragma unroll
            for (int i = 0; i < 8; i++) a[i] = Ps[k][rb + i];
#pragma unroll
            for (int j = 0; j < 4; j++) bb[j] = Vs[k][cb + j];
#pragma unroll
            for (int i = 0; i < 8; i++)
#pragma unroll
                for (int j = 0; j < 4; j++) acc[i][j] = fmaf(a[i], bb[j], acc[i][j]);
        }
        __syncthreads();
    }

#pragma unroll
    for (int i = 0; i < 8; i++)
#pragma unroll
        for (int j = 0; j < 4; j++)
            Ob[(size_t)(q0 + rb + i) * DVC + cb + j] = acc[i][j];
}

// ---------------------------------------------------------------------------
// Wvo[j,d] = sum_e Wo[j,e] * Wv[e,d]   (64 x 1024) = (64x1024) @ (1024x1024)
// 64 blocks, each owns 16 d-columns and all 64 j. e staged in 64-chunks.
// ---------------------------------------------------------------------------
__global__ __launch_bounds__(256) void wvo_kernel(const float* __restrict__ Wo,
                                                  const float* __restrict__ Wv,
                                                  float* __restrict__ Wvo)
{
    __shared__ float wvS[64][16];   // [e'][d_local]
    __shared__ float woS[64][64];   // [e'][j]

    const int d0   = blockIdx.x * 16;
    const int tid  = threadIdx.x;
    const int dloc = tid & 15;
    const int jb   = (tid >> 4) * 4;   // 0,4,...,60

    float acc[4] = {0.f, 0.f, 0.f, 0.f};

    for (int e0 = 0; e0 < D_MODELC; e0 += 64) {
        {   // wvS: 64 rows x 16 floats = 256 float4, 1 per thread
            const int r  = tid >> 2;
            const int f4 = tid & 3;
            float4 v = *(const float4*)(Wv + (size_t)(e0 + r) * D_MODELC + d0 + f4 * 4);
            *(float4*)&wvS[r][f4 * 4] = v;
        }
        {   // woS[e'][j]: 64x64 = 4096 floats, 16 per thread (transposed store)
            const int j  = tid >> 2;
            const int eb = (tid & 3) * 16;
            const float* src = Wo + (size_t)j * D_MODELC + e0 + eb;
#pragma unroll
            for (int u = 0; u < 16; u += 4) {
                float4 v = *(const float4*)(src + u);
                woS[eb + u + 0][j] = v.x; woS[eb + u + 1][j] = v.y;
                woS[eb + u + 2][j] = v.z; woS[eb + u + 3][j] = v.w;
            }
        }
        __syncthreads();

#pragma unroll 16
        for (int e = 0; e < 64; e++) {
            const float wv = wvS[e][dloc];
            acc[0] = fmaf(woS[e][jb + 0], wv, acc[0]);
            acc[1] = fmaf(woS[e][jb + 1], wv, acc[1]);
            acc[2] = fmaf(woS[e][jb + 2], wv, acc[2]);
            acc[3] = fmaf(woS[e][jb + 3], wv, acc[3]);
        }
        __syncthreads();
    }

#pragma unroll
    for (int jj = 0; jj < 4; jj++)
        Wvo[(size_t)(jb + jj) * D_MODELC + d0 + dloc] = acc[jj];
}

// ---------------------------------------------------------------------------
extern "C" void kernel_launch(void* const* d_in, const int* in_sizes, int n_in,
                              void* d_out, int out_size)
{
    const float* X  = (const float*)d_in[0];  // [4,2048,1024]
    const float* Wq = (const float*)d_in[1];  // [1024,1024]
    const float* Wk = (const float*)d_in[2];  // [1024,1024]
    const float* Wv = (const float*)d_in[3];  // [1024,1024]
    const float* Wo = (const float*)d_in[4];  // [64,1024]
    float* out = (float*)d_out;               // [4,2048,64]

    float *pQ, *pK, *pVp, *pS, *pWvo;
    cudaGetSymbolAddress((void**)&pQ,   g_Q);
    cudaGetSymbolAddress((void**)&pK,   g_K);
    cudaGetSymbolAddress((void**)&pVp,  g_Vp);
    cudaGetSymbolAddress((void**)&pS,   g_S);
    cudaGetSymbolAddress((void**)&pWvo, g_Wvo);

    const dim3 blk(256);

    // Q = X @ Wq^T, K = X @ Wk^T   [8192,1024]
    sgemm_nt<<<dim3(8, 64), blk>>>(X, Wq, pQ, MTOT, D_MODELC, D_MODELC);
    sgemm_nt<<<dim3(8, 64), blk>>>(X, Wk, pK, MTOT, D_MODELC, D_MODELC);

    // Wvo = Wo @ Wv   [64,1024]
    wvo_kernel<<<64, blk>>>(Wo, Wv, pWvo);

    // V' = X @ Wvo^T   [8192,64]
    sgemm_nt<<<dim3(1, 64), blk>>>(X, pWvo, pVp, MTOT, DVC, D_MODELC);

    // scores (causal, scaled)   [4,2048,2048]
    scores_kernel<<<dim3(16, 16, 4), blk>>>(pQ, pK, pS);

    // softmax rows (in place)
    softmax_kernel<<<MTOT, blk>>>(pS);

    // out = attn @ V'   [4,2048,64]
    ctx_kernel<<<dim3(1, 16, 4), blk>>>(pS, pVp, out);
}

// round 11
// speedup vs baseline: 1.5618x; 1.5618x over previous
#include <cuda_runtime.h>
#include <cuda_bf16.h>
#include <cstdint>
#include <cstddef>

#define D_MODELC 1024
#define SEQC     2048
#define BATCHC   4
#define DVC      64
#define MTOT     (BATCHC * SEQC)   // 8192

// ---------------------------------------------------------------------------
// Scratch (__device__ globals; no allocations allowed)
// ---------------------------------------------------------------------------
__device__ __align__(256) uint32_t g_Xh[MTOT * D_MODELC / 2];
__device__ __align__(256) uint32_t g_Xl[MTOT * D_MODELC / 2];
__device__ __align__(256) uint32_t g_Wqh[D_MODELC * D_MODELC / 2];
__device__ __align__(256) uint32_t g_Wql[D_MODELC * D_MODELC / 2];
__device__ __align__(256) uint32_t g_Wkh[D_MODELC * D_MODELC / 2];
__device__ __align__(256) uint32_t g_Wkl[D_MODELC * D_MODELC / 2];
__device__ __align__(256) uint32_t g_Qh[MTOT * D_MODELC / 2];
__device__ __align__(256) uint32_t g_Ql[MTOT * D_MODELC / 2];
__device__ __align__(256) uint32_t g_Kh[MTOT * D_MODELC / 2];
__device__ __align__(256) uint32_t g_Kl[MTOT * D_MODELC / 2];
__device__ __align__(256) float    g_Wvo[DVC * D_MODELC];
__device__ __align__(256) uint32_t g_Wvoh[DVC * D_MODELC / 2];
__device__ __align__(256) uint32_t g_Wvol[DVC * D_MODELC / 2];
__device__ __align__(256) float    g_Vp[MTOT * DVC];
__device__ __align__(256) float    g_S[BATCHC * SEQC * SEQC];

// ---------------------------------------------------------------------------
// Helpers
// ---------------------------------------------------------------------------
__device__ __forceinline__ uint32_t smem_u32(const void* p) {
    uint32_t a;
    asm("{ .reg .u64 t; cvta.to.shared.u64 t, %1; cvt.u32.u64 %0, t; }"
        : "=r"(a) : "l"(p));
    return a;
}

__device__ __forceinline__ void cp_async16(uint32_t dst, const void* src) {
    asm volatile("cp.async.cg.shared.global [%0], [%1], 16;" :: "r"(dst), "l"(src));
}
__device__ __forceinline__ void cp_commit() {
    asm volatile("cp.async.commit_group;" ::: "memory");
}
__device__ __forceinline__ void cp_wait0() {
    asm volatile("cp.async.wait_group 0;" ::: "memory");
}
__device__ __forceinline__ void cp_wait1() {
    asm volatile("cp.async.wait_group 1;" ::: "memory");
}

// bf16 mma.sync m16n8k16, fp32 accumulate (sm_80+ PTX; legal at compute_103)
__device__ __forceinline__ void mma16816(float* c, const uint32_t* a, const uint32_t* b) {
    asm volatile(
        "mma.sync.aligned.m16n8k16.row.col.f32.bf16.bf16.f32 "
        "{%0,%1,%2,%3}, {%4,%5,%6,%7}, {%8,%9}, {%0,%1,%2,%3};"
        : "+f"(c[0]), "+f"(c[1]), "+f"(c[2]), "+f"(c[3])
        : "r"(a[0]), "r"(a[1]), "r"(a[2]), "r"(a[3]), "r"(b[0]), "r"(b[1]));
}

// ---------------------------------------------------------------------------
// Shared bf16-split mainloop (mma.sync): acc += Ah@Bh^T + Ah@Bl^T + Al@Bh^T
// A tile: 128 rows, B tile: BN rows, both K-major bf16, gmem row = 128 uint4
// (1024 bf16). BK=32, 32 chunks (K=1024). 256 threads, 8 warps 2x4,
// warp tile 64 x (BN/4). Smem rows padded to 80B (20 u32): conflict-free.
// 2-stage cp.async pipeline.
// ---------------------------------------------------------------------------
#define LDSM 20                       // u32 per smem row (80B)
#define A_TILE_B 10240                // 128*80
#define STAGE_B(BN) (2 * A_TILE_B + 2 * (BN) * 80)
#define SMEM_TOT(BN) (2 * STAGE_B(BN))

template <int BN>
__device__ __forceinline__ void mainloop_mma(
    const uint4* __restrict__ Ah, const uint4* __restrict__ Al,
    const uint4* __restrict__ Bh, const uint4* __restrict__ Bl,
    float (*acc)[BN / 32][4])
{
    extern __shared__ char smch[];
    uint32_t* sm32 = (uint32_t*)smch;
    const uint32_t smb = smem_u32(smch);
    constexpr int WN    = BN / 4;        // warp n-extent
    constexpr int NI    = WN / 8;        // n-fragments per warp
    constexpr int STAGE = STAGE_B(BN);
    constexpr int BSEGS = 2 * BN * 4;    // 16B segments for both B tiles
    constexpr int BPER  = BSEGS / 256;

    const int tid  = threadIdx.x;
    const int lane = tid & 31;
    const int wid  = tid >> 5;
    const int g    = lane >> 2;
    const int tg   = lane & 3;
    const int wm0  = (wid & 1) * 64;
    const int wn0  = (wid >> 1) * WN;

#pragma unroll
    for (int mi = 0; mi < 4; mi++)
#pragma unroll
        for (int ni = 0; ni < NI; ni++)
#pragma unroll
            for (int v = 0; v < 4; v++) acc[mi][ni][v] = 0.f;

    // ---- prefetch chunk c into stage s ----
    auto prefetch = [&](int c, int s) {
        const uint32_t base = smb + s * STAGE;
        // A tiles (Ah, Al): 2 * 128 rows * 4 segs = 1024 segs
#pragma unroll
        for (int i = 0; i < 4; i++) {
            int idx  = i * 256 + tid;
            int tile = idx >> 9;          // 0 = Ah, 1 = Al
            int rem  = idx & 511;
            int r    = rem >> 2;
            int seg  = rem & 3;
            const uint4* src = (tile ? Al : Ah) + (size_t)r * 128 + c * 4 + seg;
            cp_async16(base + tile * A_TILE_B + r * 80 + seg * 16, src);
        }
        // B tiles (Bh, Bl): 2 * BN rows * 4 segs
#pragma unroll
        for (int i = 0; i < BPER; i++) {
            int idx  = i * 256 + tid;
            int tile = idx / (BN * 4);
            int rem  = idx % (BN * 4);
            int r    = rem >> 2;
            int seg  = rem & 3;
            const uint4* src = (tile ? Bl : Bh) + (size_t)r * 128 + c * 4 + seg;
            cp_async16(base + 2 * A_TILE_B + tile * (BN * 80) + r * 80 + seg * 16, src);
        }
        cp_commit();
    };

    prefetch(0, 0);

    for (int c = 0; c < 32; c++) {
        const int s = c & 1;
        if (c + 1 < 32) {
            prefetch(c + 1, s ^ 1);
            cp_wait1();
        } else {
            cp_wait0();
        }
        __syncthreads();

        uint32_t* A32h = sm32 + (s * STAGE) / 4;
        uint32_t* A32l = A32h + A_TILE_B / 4;
        uint32_t* B32h = sm32 + (s * STAGE + 2 * A_TILE_B) / 4;
        uint32_t* B32l = B32h + (BN * 80) / 4;

#pragma unroll
        for (int ks = 0; ks < 2; ks++) {
            const int kb = ks * 8 + tg;
            uint32_t ah[4][4], al[4][4], bh[NI][2], bl[NI][2];
#pragma unroll
            for (int mi = 0; mi < 4; mi++) {
                const int r = wm0 + mi * 16 + g;
                ah[mi][0] = A32h[r * LDSM + kb];
                ah[mi][1] = A32h[(r + 8) * LDSM + kb];
                ah[mi][2] = A32h[r * LDSM + kb + 4];
                ah[mi][3] = A32h[(r + 8) * LDSM + kb + 4];
                al[mi][0] = A32l[r * LDSM + kb];
                al[mi][1] = A32l[(r + 8) * LDSM + kb];
                al[mi][2] = A32l[r * LDSM + kb + 4];
                al[mi][3] = A32l[(r + 8) * LDSM + kb + 4];
            }
#pragma unroll
            for (int ni = 0; ni < NI; ni++) {
                const int n = wn0 + ni * 8 + g;
                bh[ni][0] = B32h[n * LDSM + kb];
                bh[ni][1] = B32h[n * LDSM + kb + 4];
                bl[ni][0] = B32l[n * LDSM + kb];
                bl[ni][1] = B32l[n * LDSM + kb + 4];
            }
#pragma unroll
            for (int mi = 0; mi < 4; mi++)
#pragma unroll
                for (int ni = 0; ni < NI; ni++) {
                    mma16816(acc[mi][ni], ah[mi], bh[ni]);
                    mma16816(acc[mi][ni], ah[mi], bl[ni]);
                    mma16816(acc[mi][ni], al[mi], bh[ni]);
                }
        }
        __syncthreads();
    }
}

// ---------------------------------------------------------------------------
// Projection GEMM: C = A @ B^T, output packed bf16 hi/lo. Grid (N/128, M/128).
// ---------------------------------------------------------------------------
__global__ __launch_bounds__(256, 1) void gemm_proj(
    const uint4* __restrict__ Ah, const uint4* __restrict__ Al,
    const uint4* __restrict__ Bh, const uint4* __restrict__ Bl,
    uint32_t* __restrict__ Ch, uint32_t* __restrict__ Cl)
{
    const int m0 = blockIdx.y * 128;
    const int n0 = blockIdx.x * 128;
    const int ldU = D_MODELC / 8;

    float acc[4][4][4];
    mainloop_mma<128>(Ah + (size_t)m0 * ldU, Al + (size_t)m0 * ldU,
                      Bh + (size_t)n0 * ldU, Bl + (size_t)n0 * ldU, acc);

    const int lane = threadIdx.x & 31, wid = threadIdx.x >> 5;
    const int g = lane >> 2, tg = lane & 3;
    const int wm0 = (wid & 1) * 64, wn0 = (wid >> 1) * 32;

#pragma unroll
    for (int mi = 0; mi < 4; mi++)
#pragma unroll
        for (int ni = 0; ni < 4; ni++) {
            const int col = n0 + wn0 + ni * 8 + tg * 2;
#pragma unroll
            for (int h = 0; h < 2; h++) {   // h=0: rows g, h=1: rows g+8
                const int row = m0 + wm0 + mi * 16 + g + h * 8;
                const float v0 = acc[mi][ni][h * 2 + 0];
                const float v1 = acc[mi][ni][h * 2 + 1];
                __nv_bfloat16 h0 = __float2bfloat16(v0);
                __nv_bfloat16 h1 = __float2bfloat16(v1);
                __nv_bfloat16 l0 = __float2bfloat16(v0 - __bfloat162float(h0));
                __nv_bfloat16 l1 = __float2bfloat16(v1 - __bfloat162float(h1));
                const size_t idx = ((size_t)row * D_MODELC + col) / 2;
                Ch[idx] = (uint32_t)__bfloat16_as_ushort(h0) |
                          ((uint32_t)__bfloat16_as_ushort(h1) << 16);
                Cl[idx] = (uint32_t)__bfloat16_as_ushort(l0) |
                          ((uint32_t)__bfloat16_as_ushort(l1) << 16);
            }
        }
}

// ---------------------------------------------------------------------------
// Causal scores: S[b,q,k] = (Q·K)/32 for k<=q. Grid (16,16,4), skip bx>by.
// ---------------------------------------------------------------------------
__global__ __launch_bounds__(256, 1) void gemm_scores(
    const uint4* __restrict__ Qh, const uint4* __restrict__ Ql,
    const uint4* __restrict__ Kh, const uint4* __restrict__ Kl,
    float* __restrict__ S)
{
    if (blockIdx.x > blockIdx.y) return;
    const int b  = blockIdx.z;
    const int m0 = blockIdx.y * 128;
    const int n0 = blockIdx.x * 128;
    const int ldU = D_MODELC / 8;
    const size_t boff = (size_t)b * SEQC * ldU;

    float acc[4][4][4];
    mainloop_mma<128>(Qh + boff + (size_t)m0 * ldU, Ql + boff + (size_t)m0 * ldU,
                      Kh + boff + (size_t)n0 * ldU, Kl + boff + (size_t)n0 * ldU, acc);

    const int lane = threadIdx.x & 31, wid = threadIdx.x >> 5;
    const int g = lane >> 2, tg = lane & 3;
    const int wm0 = (wid & 1) * 64, wn0 = (wid >> 1) * 32;
    float* Sb = S + (size_t)b * SEQC * SEQC;

#pragma unroll
    for (int mi = 0; mi < 4; mi++)
#pragma unroll
        for (int ni = 0; ni < 4; ni++) {
            const int col = n0 + wn0 + ni * 8 + tg * 2;
#pragma unroll
            for (int h = 0; h < 2; h++) {
                const int q = m0 + wm0 + mi * 16 + g + h * 8;
                float* R = Sb + (size_t)q * SEQC;
                if (col     <= q) R[col]     = acc[mi][ni][h * 2 + 0] * 0.03125f;
                if (col + 1 <= q) R[col + 1] = acc[mi][ni][h * 2 + 1] * 0.03125f;
            }
        }
}

// ---------------------------------------------------------------------------
// V' GEMM: Vp = X @ Wvo^T  [8192,64] fp32. BN=64, grid (1,64).
// ---------------------------------------------------------------------------
__global__ __launch_bounds__(256, 1) void gemm_vp(
    const uint4* __restrict__ Ah, const uint4* __restrict__ Al,
    const uint4* __restrict__ Bh, const uint4* __restrict__ Bl,
    float* __restrict__ Vp)
{
    const int m0 = blockIdx.y * 128;
    const int ldU = D_MODELC / 8;

    float acc[4][2][4];
    mainloop_mma<64>(Ah + (size_t)m0 * ldU, Al + (size_t)m0 * ldU, Bh, Bl, acc);

    const int lane = threadIdx.x & 31, wid = threadIdx.x >> 5;
    const int g = lane >> 2, tg = lane & 3;
    const int wm0 = (wid & 1) * 64, wn0 = (wid >> 1) * 16;

#pragma unroll
    for (int mi = 0; mi < 4; mi++)
#pragma unroll
        for (int ni = 0; ni < 2; ni++) {
            const int col = wn0 + ni * 8 + tg * 2;
#pragma unroll
            for (int h = 0; h < 2; h++) {
                const int row = m0 + wm0 + mi * 16 + g + h * 8;
                Vp[(size_t)row * DVC + col]     = acc[mi][ni][h * 2 + 0];
                Vp[(size_t)row * DVC + col + 1] = acc[mi][ni][h * 2 + 1];
            }
        }
}

// ---------------------------------------------------------------------------
// fp32 -> bf16 hi/lo split (packed pairs). One float4 per thread.
// ---------------------------------------------------------------------------
__global__ __launch_bounds__(256) void cvt_pair(const float4* __restrict__ in,
                                                uint32_t* __restrict__ hi,
                                                uint32_t* __restrict__ lo, int n4)
{
    int i = blockIdx.x * blockDim.x + threadIdx.x;
    if (i >= n4) return;
    float4 v = in[i];
    __nv_bfloat16 h0 = __float2bfloat16(v.x), h1 = __float2bfloat16(v.y);
    __nv_bfloat16 h2 = __float2bfloat16(v.z), h3 = __float2bfloat16(v.w);
    __nv_bfloat16 l0 = __float2bfloat16(v.x - __bfloat162float(h0));
    __nv_bfloat16 l1 = __float2bfloat16(v.y - __bfloat162float(h1));
    __nv_bfloat16 l2 = __float2bfloat16(v.z - __bfloat162float(h2));
    __nv_bfloat16 l3 = __float2bfloat16(v.w - __bfloat162float(h3));
    hi[2 * i]     = (uint32_t)__bfloat16_as_ushort(h0) | ((uint32_t)__bfloat16_as_ushort(h1) << 16);
    hi[2 * i + 1] = (uint32_t)__bfloat16_as_ushort(h2) | ((uint32_t)__bfloat16_as_ushort(h3) << 16);
    lo[2 * i]     = (uint32_t)__bfloat16_as_ushort(l0) | ((uint32_t)__bfloat16_as_ushort(l1) << 16);
    lo[2 * i + 1] = (uint32_t)__bfloat16_as_ushort(l2) | ((uint32_t)__bfloat16_as_ushort(l3) << 16);
}

// ---------------------------------------------------------------------------
// Wvo[j,d] = sum_e Wo[j,e] * Wv[e,d]   (64 x 1024), fp32 (tiny)
// ---------------------------------------------------------------------------
__global__ __launch_bounds__(256) void wvo_kernel(const float* __restrict__ Wo,
                                                  const float* __restrict__ Wv,
                                                  float* __restrict__ Wvo)
{
    __shared__ float wvS[64][16];
    __shared__ float woS[64][64];

    const int d0   = blockIdx.x * 16;
    const int tid  = threadIdx.x;
    const int dloc = tid & 15;
    const int jb   = (tid >> 4) * 4;

    float acc[4] = {0.f, 0.f, 0.f, 0.f};

    for (int e0 = 0; e0 < D_MODELC; e0 += 64) {
        {
            const int r  = tid >> 2;
            const int f4 = tid & 3;
            float4 v = *(const float4*)(Wv + (size_t)(e0 + r) * D_MODELC + d0 + f4 * 4);
            *(float4*)&wvS[r][f4 * 4] = v;
        }
        {
            const int j  = tid >> 2;
            const int eb = (tid & 3) * 16;
            const float* src = Wo + (size_t)j * D_MODELC + e0 + eb;
#pragma unroll
            for (int u = 0; u < 16; u += 4) {
                float4 v = *(const float4*)(src + u);
                woS[eb + u + 0][j] = v.x; woS[eb + u + 1][j] = v.y;
                woS[eb + u + 2][j] = v.z; woS[eb + u + 3][j] = v.w;
            }
        }
        __syncthreads();

#pragma unroll 16
        for (int e = 0; e < 64; e++) {
            const float wv = wvS[e][dloc];
            acc[0] = fmaf(woS[e][jb + 0], wv, acc[0]);
            acc[1] = fmaf(woS[e][jb + 1], wv, acc[1]);
            acc[2] = fmaf(woS[e][jb + 2], wv, acc[2]);
            acc[3] = fmaf(woS[e][jb + 3], wv, acc[3]);
        }
        __syncthreads();
    }

#pragma unroll
    for (int jj = 0; jj < 4; jj++)
        Wvo[(size_t)(jb + jj) * D_MODELC + d0 + dloc] = acc[jj];
}

// ---------------------------------------------------------------------------
// Row softmax over valid prefix [0, q]; zeros beyond. One block per row.
// Warp-shuffle reductions (2 syncthreads total).
// ---------------------------------------------------------------------------
__global__ __launch_bounds__(256) void softmax_kernel(float* __restrict__ S)
{
    __shared__ float buf[SEQC];
    __shared__ float red[8];

    const int row = blockIdx.x;
    const int b   = row / SEQC;
    const int q   = row % SEQC;
    float* R = S + (size_t)b * SEQC * SEQC + (size_t)q * SEQC;
    const int n   = q + 1;
    const int tid = threadIdx.x;
    const int lane = tid & 31, wrp = tid >> 5;

    float lmax = -1e30f;
    for (int k = tid; k < n; k += 256) {
        float v = R[k];
        buf[k] = v;
        lmax = fmaxf(lmax, v);
    }
#pragma unroll
    for (int o = 16; o > 0; o >>= 1)
        lmax = fmaxf(lmax, __shfl_xor_sync(0xffffffffu, lmax, o));
    if (lane == 0) red[wrp] = lmax;
    __syncthreads();
    float m = red[lane & 7];
#pragma unroll
    for (int o = 4; o > 0; o >>= 1)
        m = fmaxf(m, __shfl_xor_sync(0xffffffffu, m, o));

    float lsum = 0.f;
    for (int k = tid; k < n; k += 256) {
        float e = __expf(buf[k] - m);
        buf[k] = e;
        lsum += e;
    }
#pragma unroll
    for (int o = 16; o > 0; o >>= 1)
        lsum += __shfl_xor_sync(0xffffffffu, lsum, o);
    if (lane == 0) red[wrp] = lsum;
    __syncthreads();
    float tot = red[lane & 7];
#pragma unroll
    for (int o = 4; o > 0; o >>= 1)
        tot += __shfl_xor_sync(0xffffffffu, tot, o);
    const float inv = 1.f / tot;

    for (int k = tid; k < n; k += 256)        R[k] = buf[k] * inv;
    for (int k = n + tid; k < SEQC; k += 256) R[k] = 0.f;
}

// ---------------------------------------------------------------------------
// Context: O[b,q,j] = sum_k P[b,q,k] * Vp[b,k,j]. Tile 64q x 64j, BK=16,
// 256 threads, 4x4 micro. Grid (1, 32, 4). Causal k-skip.
// ---------------------------------------------------------------------------
__global__ __launch_bounds__(256) void ctx_kernel(const float* __restrict__ P,
                                                  const float* __restrict__ Vp,
                                                  float* __restrict__ O)
{
    __shared__ float Ps[16][66];
    __shared__ float Vs[16][64];

    const int b  = blockIdx.z;
    const int q0 = blockIdx.y * 64;
    const float* Pb = P  + (size_t)b * SEQC * SEQC;
    const float* Vb = Vp + (size_t)b * SEQC * DVC;
    float*       Ob = O  + (size_t)b * SEQC * DVC;

    const int tid = threadIdx.x;
    const int ty  = tid >> 4;
    const int tx  = tid & 15;
    const int rb  = ty * 4;
    const int cb  = tx * 4;

    float acc[4][4];
#pragma unroll
    for (int i = 0; i < 4; i++)
#pragma unroll
        for (int j = 0; j < 4; j++) acc[i][j] = 0.f;

    const int kmax = (q0 + 64 < SEQC) ? (q0 + 64) : SEQC;
    for (int k0 = 0; k0 < kmax; k0 += 16) {
        {
            const int r  = tid >> 2;
            const int f4 = tid & 3;
            float4 v = *(const float4*)(Pb + (size_t)(q0 + r) * SEQC + k0 + f4 * 4);
            Ps[f4 * 4 + 0][r] = v.x; Ps[f4 * 4 + 1][r] = v.y;
            Ps[f4 * 4 + 2][r] = v.z; Ps[f4 * 4 + 3][r] = v.w;
        }
        {
            const int r  = tid >> 4;
            const int f4 = tid & 15;
            float4 v = *(const float4*)(Vb + (size_t)(k0 + r) * DVC + f4 * 4);
            *(float4*)&Vs[r][f4 * 4] = v;
        }
        __syncthreads();

#pragma unroll
        for (int k = 0; k < 16; k++) {
            float a[4], bb[4];
#pragma unroll
            for (int i = 0; i < 4; i++) a[i] = Ps[k][rb + i];
#pragma unroll
            for (int j = 0; j < 4; j++) bb[j] = Vs[k][cb + j];
#pragma unroll
            for (int i = 0; i < 4; i++)
#pragma unroll
                for (int j = 0; j < 4; j++) acc[i][j] = fmaf(a[i], bb[j], acc[i][j]);
        }
        __syncthreads();
    }

#pragma unroll
    for (int i = 0; i < 4; i++)
#pragma unroll
        for (int j = 0; j < 4; j++)
            Ob[(size_t)(q0 + rb + i) * DVC + cb + j] = acc[i][j];
}

// ---------------------------------------------------------------------------
extern "C" void kernel_launch(void* const* d_in, const int* in_sizes, int n_in,
                              void* d_out, int out_size)
{
    const float* X  = (const float*)d_in[0];
    const float* Wq = (const float*)d_in[1];
    const float* Wk = (const float*)d_in[2];
    const float* Wv = (const float*)d_in[3];
    const float* Wo = (const float*)d_in[4];
    float* out = (float*)d_out;

    void *pXh, *pXl, *pWqh, *pWql, *pWkh, *pWkl, *pQh, *pQl, *pKh, *pKl;
    void *pWvo, *pWvoh, *pWvol, *pVp, *pS;
    cudaGetSymbolAddress(&pXh,  g_Xh);   cudaGetSymbolAddress(&pXl,  g_Xl);
    cudaGetSymbolAddress(&pWqh, g_Wqh);  cudaGetSymbolAddress(&pWql, g_Wql);
    cudaGetSymbolAddress(&pWkh, g_Wkh);  cudaGetSymbolAddress(&pWkl, g_Wkl);
    cudaGetSymbolAddress(&pQh,  g_Qh);   cudaGetSymbolAddress(&pQl,  g_Ql);
    cudaGetSymbolAddress(&pKh,  g_Kh);   cudaGetSymbolAddress(&pKl,  g_Kl);
    cudaGetSymbolAddress(&pWvo, g_Wvo);
    cudaGetSymbolAddress(&pWvoh, g_Wvoh); cudaGetSymbolAddress(&pWvol, g_Wvol);
    cudaGetSymbolAddress(&pVp,  g_Vp);   cudaGetSymbolAddress(&pS,   g_S);

    cudaFuncSetAttribute(gemm_proj,   cudaFuncAttributeMaxDynamicSharedMemorySize, SMEM_TOT(128));
    cudaFuncSetAttribute(gemm_scores, cudaFuncAttributeMaxDynamicSharedMemorySize, SMEM_TOT(128));
    cudaFuncSetAttribute(gemm_vp,     cudaFuncAttributeMaxDynamicSharedMemorySize, SMEM_TOT(64));

    // Split inputs into bf16 hi/lo
    cvt_pair<<<MTOT * D_MODELC / 4 / 256, 256>>>((const float4*)X,  (uint32_t*)pXh,  (uint32_t*)pXl,  MTOT * D_MODELC / 4);
    cvt_pair<<<D_MODELC * D_MODELC / 4 / 256, 256>>>((const float4*)Wq, (uint32_t*)pWqh, (uint32_t*)pWql, D_MODELC * D_MODELC / 4);
    cvt_pair<<<D_MODELC * D_MODELC / 4 / 256, 256>>>((const float4*)Wk, (uint32_t*)pWkh, (uint32_t*)pWkl, D_MODELC * D_MODELC / 4);

    // Wvo = Wo @ Wv (fp32, tiny), then split
    wvo_kernel<<<64, 256>>>(Wo, Wv, (float*)pWvo);
    cvt_pair<<<DVC * D_MODELC / 4 / 256, 256>>>((const float4*)pWvo, (uint32_t*)pWvoh, (uint32_t*)pWvol, DVC * D_MODELC / 4);

    // Q/K projections (tensor path via mma.sync), outputs bf16 hi/lo
    gemm_proj<<<dim3(8, 64), 256, SMEM_TOT(128)>>>(
        (const uint4*)pXh, (const uint4*)pXl, (const uint4*)pWqh, (const uint4*)pWql,
        (uint32_t*)pQh, (uint32_t*)pQl);
    gemm_proj<<<dim3(8, 64), 256, SMEM_TOT(128)>>>(
        (const uint4*)pXh, (const uint4*)pXl, (const uint4*)pWkh, (const uint4*)pWkl,
        (uint32_t*)pKh, (uint32_t*)pKl);

    // V' = X @ Wvo^T (tensor path), fp32 out
    gemm_vp<<<dim3(1, 64), 256, SMEM_TOT(64)>>>(
        (const uint4*)pXh, (const uint4*)pXl, (const uint4*)pWvoh, (const uint4*)pWvol,
        (float*)pVp);

    // Causal scores (tensor path)
    gemm_scores<<<dim3(16, 16, 4), 256, SMEM_TOT(128)>>>(
        (const uint4*)pQh, (const uint4*)pQl, (const uint4*)pKh, (const uint4*)pKl,
        (float*)pS);

    // Softmax rows (in place)
    softmax_kernel<<<MTOT, 256>>>((float*)pS);

    // out = attn @ V'
    ctx_kernel<<<dim3(1, 32, 4), 256>>>((const float*)pS, (const float*)pVp, out);
}

// round 15
// speedup vs baseline: 2.2732x; 1.4555x over previous
#include <cuda_runtime.h>
#include <cuda_bf16.h>
#include <cstdint>
#include <cstddef>

#define D_MODELC 1024
#define SEQC     2048
#define BATCHC   4
#define DVC      64
#define MTOT     (BATCHC * SEQC)   // 8192

// ---------------------------------------------------------------------------
// Scratch (__device__ globals; no allocations allowed)
// ---------------------------------------------------------------------------
__device__ __align__(256) uint32_t g_Xh[MTOT * D_MODELC / 2];
__device__ __align__(256) uint32_t g_Xl[MTOT * D_MODELC / 2];
__device__ __align__(256) uint32_t g_Wqh[D_MODELC * D_MODELC / 2];
__device__ __align__(256) uint32_t g_Wql[D_MODELC * D_MODELC / 2];
__device__ __align__(256) uint32_t g_Wkh[D_MODELC * D_MODELC / 2];
__device__ __align__(256) uint32_t g_Wkl[D_MODELC * D_MODELC / 2];
__device__ __align__(256) uint32_t g_Qh[MTOT * D_MODELC / 2];
__device__ __align__(256) uint32_t g_Ql[MTOT * D_MODELC / 2];
__device__ __align__(256) uint32_t g_Kh[MTOT * D_MODELC / 2];
__device__ __align__(256) uint32_t g_Kl[MTOT * D_MODELC / 2];
__device__ __align__(256) float    g_Wvo[DVC * D_MODELC];
__device__ __align__(256) uint32_t g_Wvoh[DVC * D_MODELC / 2];
__device__ __align__(256) uint32_t g_Wvol[DVC * D_MODELC / 2];
__device__ __align__(256) float    g_Vp[MTOT * DVC];
__device__ __align__(256) float    g_S[BATCHC * SEQC * SEQC];

// ---------------------------------------------------------------------------
// Helpers
// ---------------------------------------------------------------------------
__device__ __forceinline__ uint32_t smem_u32(const void* p) {
    uint32_t a;
    asm("{ .reg .u64 t; cvta.to.shared.u64 t, %1; cvt.u32.u64 %0, t; }"
        : "=r"(a) : "l"(p));
    return a;
}

__device__ __forceinline__ void cp_async16(uint32_t dst, const void* src) {
    asm volatile("cp.async.cg.shared.global [%0], [%1], 16;" :: "r"(dst), "l"(src));
}
__device__ __forceinline__ void cp_commit() {
    asm volatile("cp.async.commit_group;" ::: "memory");
}
__device__ __forceinline__ void cp_wait0() {
    asm volatile("cp.async.wait_group 0;" ::: "memory");
}
__device__ __forceinline__ void cp_wait1() {
    asm volatile("cp.async.wait_group 1;" ::: "memory");
}
__device__ __forceinline__ void cp_wait2() {
    asm volatile("cp.async.wait_group 2;" ::: "memory");
}

// bf16 mma.sync m16n8k16, fp32 accumulate (sm_80+ PTX; legal at compute_103)
__device__ __forceinline__ void mma16816(float* c, const uint32_t* a, const uint32_t* b) {
    asm volatile(
        "mma.sync.aligned.m16n8k16.row.col.f32.bf16.bf16.f32 "
        "{%0,%1,%2,%3}, {%4,%5,%6,%7}, {%8,%9}, {%0,%1,%2,%3};"
        : "+f"(c[0]), "+f"(c[1]), "+f"(c[2]), "+f"(c[3])
        : "r"(a[0]), "r"(a[1]), "r"(a[2]), "r"(a[3]), "r"(b[0]), "r"(b[1]));
}

// ldmatrix x4: four 8x8 b16 tiles, lane i of each 8-lane group supplies row addr
__device__ __forceinline__ void ldsm4(uint32_t* r, uint32_t addr) {
    asm volatile("ldmatrix.sync.aligned.m8n8.x4.shared.b16 {%0,%1,%2,%3}, [%4];"
        : "=r"(r[0]), "=r"(r[1]), "=r"(r[2]), "=r"(r[3]) : "r"(addr));
}

// ---------------------------------------------------------------------------
// Shared bf16-split mainloop (mma.sync): acc += Ah@Bh^T + Ah@Bl^T + Al@Bh^T
// A tile: 128 rows, B tile: BN rows, both K-major bf16, gmem row = 128 uint4
// (1024 bf16). BK=32, 32 chunks (K=1024). 256 threads, 8 warps 2x4,
// warp tile 64 x (BN/4). Smem rows padded to 80B: conflict-free, 16B-aligned.
// 3-stage cp.async pipeline; ldmatrix.x4 fragment loads.
// ---------------------------------------------------------------------------
#define LDSM 20                       // u32 per smem row (80B)
#define A_TILE_B 10240                // 128*80
#define STAGE_B(BN) (2 * A_TILE_B + 2 * (BN) * 80)
#define SMEM_TOT(BN) (3 * STAGE_B(BN))

template <int BN>
__device__ __forceinline__ void mainloop_mma(
    const uint4* __restrict__ Ah, const uint4* __restrict__ Al,
    const uint4* __restrict__ Bh, const uint4* __restrict__ Bl,
    float (*acc)[BN / 32][4])
{
    extern __shared__ char smch[];
    const uint32_t smb = smem_u32(smch);
    constexpr int WN    = BN / 4;        // warp n-extent
    constexpr int NI    = WN / 8;        // n-fragments per warp
    constexpr int STAGE = STAGE_B(BN);
    constexpr int BSEGS = 2 * BN * 4;    // 16B segments for both B tiles
    constexpr int BPER  = BSEGS / 256;

    const int tid  = threadIdx.x;
    const int lane = tid & 31;
    const int wid  = tid >> 5;
    const int wm0  = (wid & 1) * 64;
    const int wn0  = (wid >> 1) * WN;

    // ldmatrix lane-address offsets (bytes within a tile)
    // A (16x16): mat0 = m-lo/k-lo, mat1 = m-hi/k-lo, mat2 = m-lo/k-hi, mat3 = m-hi/k-hi
    const int a_off = (wm0 + ((lane >> 3) & 1) * 8 + (lane & 7)) * 80 + (lane >> 4) * 16;
    // B (2x n8k16): mat0 = ni0/k-lo, mat1 = ni0/k-hi, mat2 = ni1/k-lo, mat3 = ni1/k-hi
    const int b_off = (wn0 + (lane >> 4) * 8 + (lane & 7)) * 80 + ((lane >> 3) & 1) * 16;

#pragma unroll
    for (int mi = 0; mi < 4; mi++)
#pragma unroll
        for (int ni = 0; ni < NI; ni++)
#pragma unroll
            for (int v = 0; v < 4; v++) acc[mi][ni][v] = 0.f;

    // ---- prefetch chunk c into stage s ----
    auto prefetch = [&](int c, int s) {
        const uint32_t base = smb + s * STAGE;
        // A tiles (Ah, Al): 2 * 128 rows * 4 segs = 1024 segs
#pragma unroll
        for (int i = 0; i < 4; i++) {
            int idx  = i * 256 + tid;
            int tile = idx >> 9;          // 0 = Ah, 1 = Al
            int rem  = idx & 511;
            int r    = rem >> 2;
            int seg  = rem & 3;
            const uint4* src = (tile ? Al : Ah) + (size_t)r * 128 + c * 4 + seg;
            cp_async16(base + tile * A_TILE_B + r * 80 + seg * 16, src);
        }
        // B tiles (Bh, Bl): 2 * BN rows * 4 segs
#pragma unroll
        for (int i = 0; i < BPER; i++) {
            int idx  = i * 256 + tid;
            int tile = idx / (BN * 4);
            int rem  = idx % (BN * 4);
            int r    = rem >> 2;
            int seg  = rem & 3;
            const uint4* src = (tile ? Bl : Bh) + (size_t)r * 128 + c * 4 + seg;
            cp_async16(base + 2 * A_TILE_B + tile * (BN * 80) + r * 80 + seg * 16, src);
        }
        cp_commit();
    };

    prefetch(0, 0);
    prefetch(1, 1);

    for (int c = 0; c < 32; c++) {
        const int s = c - (c / 3) * 3;    // c % 3
        if (c + 2 < 32) {
            prefetch(c + 2, (c + 2) % 3);
            cp_wait2();
        } else if (c + 1 < 32) {
            cp_wait1();
        } else {
            cp_wait0();
        }
        __syncthreads();

        const uint32_t Ahb = smb + s * STAGE;
        const uint32_t Alb = Ahb + A_TILE_B;
        const uint32_t Bhb = Ahb + 2 * A_TILE_B;
        const uint32_t Blb = Bhb + BN * 80;

#pragma unroll
        for (int ks = 0; ks < 2; ks++) {
            const int koff = ks * 32;
            uint32_t ah[4][4], al[4][4], bh[NI][2], bl[NI][2];
#pragma unroll
            for (int mi = 0; mi < 4; mi++) {
                ldsm4(ah[mi], Ahb + a_off + mi * 1280 + koff);
                ldsm4(al[mi], Alb + a_off + mi * 1280 + koff);
            }
#pragma unroll
            for (int p = 0; p < NI / 2; p++) {
                ldsm4(&bh[2 * p][0], Bhb + b_off + p * 1280 + koff);
                ldsm4(&bl[2 * p][0], Blb + b_off + p * 1280 + koff);
            }
#pragma unroll
            for (int mi = 0; mi < 4; mi++)
#pragma unroll
                for (int ni = 0; ni < NI; ni++) {
                    mma16816(acc[mi][ni], ah[mi], bh[ni]);
                    mma16816(acc[mi][ni], ah[mi], bl[ni]);
                    mma16816(acc[mi][ni], al[mi], bh[ni]);
                }
        }
        __syncthreads();
    }
}

// ---------------------------------------------------------------------------
// Projection GEMM: C = A @ B^T, output packed bf16 hi/lo. Grid (N/128, M/128).
// ---------------------------------------------------------------------------
__global__ __launch_bounds__(256, 1) void gemm_proj(
    const uint4* __restrict__ Ah, const uint4* __restrict__ Al,
    const uint4* __restrict__ Bh, const uint4* __restrict__ Bl,
    uint32_t* __restrict__ Ch, uint32_t* __restrict__ Cl)
{
    const int m0 = blockIdx.y * 128;
    const int n0 = blockIdx.x * 128;
    const int ldU = D_MODELC / 8;

    float acc[4][4][4];
    mainloop_mma<128>(Ah + (size_t)m0 * ldU, Al + (size_t)m0 * ldU,
                      Bh + (size_t)n0 * ldU, Bl + (size_t)n0 * ldU, acc);

    const int lane = threadIdx.x & 31, wid = threadIdx.x >> 5;
    const int g = lane >> 2, tg = lane & 3;
    const int wm0 = (wid & 1) * 64, wn0 = (wid >> 1) * 32;

#pragma unroll
    for (int mi = 0; mi < 4; mi++)
#pragma unroll
        for (int ni = 0; ni < 4; ni++) {
            const int col = n0 + wn0 + ni * 8 + tg * 2;
#pragma unroll
            for (int h = 0; h < 2; h++) {   // h=0: rows g, h=1: rows g+8
                const int row = m0 + wm0 + mi * 16 + g + h * 8;
                const float v0 = acc[mi][ni][h * 2 + 0];
                const float v1 = acc[mi][ni][h * 2 + 1];
                __nv_bfloat16 h0 = __float2bfloat16(v0);
                __nv_bfloat16 h1 = __float2bfloat16(v1);
                __nv_bfloat16 l0 = __float2bfloat16(v0 - __bfloat162float(h0));
                __nv_bfloat16 l1 = __float2bfloat16(v1 - __bfloat162float(h1));
                const size_t idx = ((size_t)row * D_MODELC + col) / 2;
                Ch[idx] = (uint32_t)__bfloat16_as_ushort(h0) |
                          ((uint32_t)__bfloat16_as_ushort(h1) << 16);
                Cl[idx] = (uint32_t)__bfloat16_as_ushort(l0) |
                          ((uint32_t)__bfloat16_as_ushort(l1) << 16);
            }
        }
}

// ---------------------------------------------------------------------------
// Causal scores: S[b,q,k] = (Q·K)/32 for k<=q. Grid (16,16,4), skip bx>by.
// ---------------------------------------------------------------------------
__global__ __launch_bounds__(256, 1) void gemm_scores(
    const uint4* __restrict__ Qh, const uint4* __restrict__ Ql,
    const uint4* __restrict__ Kh, const uint4* __restrict__ Kl,
    float* __restrict__ S)
{
    if (blockIdx.x > blockIdx.y) return;
    const int b  = blockIdx.z;
    const int m0 = blockIdx.y * 128;
    const int n0 = blockIdx.x * 128;
    const int ldU = D_MODELC / 8;
    const size_t boff = (size_t)b * SEQC * ldU;

    float acc[4][4][4];
    mainloop_mma<128>(Qh + boff + (size_t)m0 * ldU, Ql + boff + (size_t)m0 * ldU,
                      Kh + boff + (size_t)n0 * ldU, Kl + boff + (size_t)n0 * ldU, acc);

    const int lane = threadIdx.x & 31, wid = threadIdx.x >> 5;
    const int g = lane >> 2, tg = lane & 3;
    const int wm0 = (wid & 1) * 64, wn0 = (wid >> 1) * 32;
    float* Sb = S + (size_t)b * SEQC * SEQC;

#pragma unroll
    for (int mi = 0; mi < 4; mi++)
#pragma unroll
        for (int ni = 0; ni < 4; ni++) {
            const int col = n0 + wn0 + ni * 8 + tg * 2;
#pragma unroll
            for (int h = 0; h < 2; h++) {
                const int q = m0 + wm0 + mi * 16 + g + h * 8;
                float* R = Sb + (size_t)q * SEQC;
                if (col     <= q) R[col]     = acc[mi][ni][h * 2 + 0] * 0.03125f;
                if (col + 1 <= q) R[col + 1] = acc[mi][ni][h * 2 + 1] * 0.03125f;
            }
        }
}

// ---------------------------------------------------------------------------
// V' GEMM: Vp = X @ Wvo^T  [8192,64] fp32. BN=64, grid (1,64).
// ---------------------------------------------------------------------------
__global__ __launch_bounds__(256, 1) void gemm_vp(
    const uint4* __restrict__ Ah, const uint4* __restrict__ Al,
    const uint4* __restrict__ Bh, const uint4* __restrict__ Bl,
    float* __restrict__ Vp)
{
    const int m0 = blockIdx.y * 128;
    const int ldU = D_MODELC / 8;

    float acc[4][2][4];
    mainloop_mma<64>(Ah + (size_t)m0 * ldU, Al + (size_t)m0 * ldU, Bh, Bl, acc);

    const int lane = threadIdx.x & 31, wid = threadIdx.x >> 5;
    const int g = lane >> 2, tg = lane & 3;
    const int wm0 = (wid & 1) * 64, wn0 = (wid >> 1) * 16;

#pragma unroll
    for (int mi = 0; mi < 4; mi++)
#pragma unroll
        for (int ni = 0; ni < 2; ni++) {
            const int col = wn0 + ni * 8 + tg * 2;
#pragma unroll
            for (int h = 0; h < 2; h++) {
                const int row = m0 + wm0 + mi * 16 + g + h * 8;
                Vp[(size_t)row * DVC + col]     = acc[mi][ni][h * 2 + 0];
                Vp[(size_t)row * DVC + col + 1] = acc[mi][ni][h * 2 + 1];
            }
        }
}

// ---------------------------------------------------------------------------
// fp32 -> bf16 hi/lo split (packed pairs). One float4 per thread.
// ---------------------------------------------------------------------------
__global__ __launch_bounds__(256) void cvt_pair(const float4* __restrict__ in,
                                                uint32_t* __restrict__ hi,
                                                uint32_t* __restrict__ lo, int n4)
{
    int i = blockIdx.x * blockDim.x + threadIdx.x;
    if (i >= n4) return;
    float4 v = in[i];
    __nv_bfloat16 h0 = __float2bfloat16(v.x), h1 = __float2bfloat16(v.y);
    __nv_bfloat16 h2 = __float2bfloat16(v.z), h3 = __float2bfloat16(v.w);
    __nv_bfloat16 l0 = __float2bfloat16(v.x - __bfloat162float(h0));
    __nv_bfloat16 l1 = __float2bfloat16(v.y - __bfloat162float(h1));
    __nv_bfloat16 l2 = __float2bfloat16(v.z - __bfloat162float(h2));
    __nv_bfloat16 l3 = __float2bfloat16(v.w - __bfloat162float(h3));
    hi[2 * i]     = (uint32_t)__bfloat16_as_ushort(h0) | ((uint32_t)__bfloat16_as_ushort(h1) << 16);
    hi[2 * i + 1] = (uint32_t)__bfloat16_as_ushort(h2) | ((uint32_t)__bfloat16_as_ushort(h3) << 16);
    lo[2 * i]     = (uint32_t)__bfloat16_as_ushort(l0) | ((uint32_t)__bfloat16_as_ushort(l1) << 16);
    lo[2 * i + 1] = (uint32_t)__bfloat16_as_ushort(l2) | ((uint32_t)__bfloat16_as_ushort(l3) << 16);
}

// ---------------------------------------------------------------------------
// Wvo[j,d] = sum_e Wo[j,e] * Wv[e,d]   (64 x 1024), fp32.
// One thread per output element; 256 blocks x 256 threads. Warp reads
// coalesced Wv rows; Wo row element broadcast. Latency hidden by unroll.
// ---------------------------------------------------------------------------
__global__ __launch_bounds__(256) void wvo_kernel(const float* __restrict__ Wo,
                                                  const float* __restrict__ Wv,
                                                  float* __restrict__ Wvo)
{
    const int idx = blockIdx.x * 256 + threadIdx.x;   // 0..65535
    const int j = idx >> 10;
    const int d = idx & 1023;
    const float* wo = Wo + (size_t)j * D_MODELC;
    const float* wv = Wv + d;

    float s0 = 0.f, s1 = 0.f, s2 = 0.f, s3 = 0.f;
#pragma unroll 4
    for (int e = 0; e < D_MODELC; e += 4) {
        s0 = fmaf(__ldg(wo + e + 0), __ldg(wv + (size_t)(e + 0) * D_MODELC), s0);
        s1 = fmaf(__ldg(wo + e + 1), __ldg(wv + (size_t)(e + 1) * D_MODELC), s1);
        s2 = fmaf(__ldg(wo + e + 2), __ldg(wv + (size_t)(e + 2) * D_MODELC), s2);
        s3 = fmaf(__ldg(wo + e + 3), __ldg(wv + (size_t)(e + 3) * D_MODELC), s3);
    }
    Wvo[idx] = (s0 + s1) + (s2 + s3);
}

// ---------------------------------------------------------------------------
// Row softmax over valid prefix [0, q]; zeros beyond. One block per row.
// Warp-shuffle reductions (2 syncthreads total).
// ---------------------------------------------------------------------------
__global__ __launch_bounds__(256) void softmax_kernel(float* __restrict__ S)
{
    __shared__ float buf[SEQC];
    __shared__ float red[8];

    const int row = blockIdx.x;
    const int b   = row / SEQC;
    const int q   = row % SEQC;
    float* R = S + (size_t)b * SEQC * SEQC + (size_t)q * SEQC;
    const int n   = q + 1;
    const int tid = threadIdx.x;
    const int lane = tid & 31, wrp = tid >> 5;

    float lmax = -1e30f;
    for (int k = tid; k < n; k += 256) {
        float v = R[k];
        buf[k] = v;
        lmax = fmaxf(lmax, v);
    }
#pragma unroll
    for (int o = 16; o > 0; o >>= 1)
        lmax = fmaxf(lmax, __shfl_xor_sync(0xffffffffu, lmax, o));
    if (lane == 0) red[wrp] = lmax;
    __syncthreads();
    float m = red[lane & 7];
#pragma unroll
    for (int o = 4; o > 0; o >>= 1)
        m = fmaxf(m, __shfl_xor_sync(0xffffffffu, m, o));

    float lsum = 0.f;
    for (int k = tid; k < n; k += 256) {
        float e = __expf(buf[k] - m);
        buf[k] = e;
        lsum += e;
    }
#pragma unroll
    for (int o = 16; o > 0; o >>= 1)
        lsum += __shfl_xor_sync(0xffffffffu, lsum, o);
    if (lane == 0) red[wrp] = lsum;
    __syncthreads();
    float tot = red[lane & 7];
#pragma unroll
    for (int o = 4; o > 0; o >>= 1)
        tot += __shfl_xor_sync(0xffffffffu, tot, o);
    const float inv = 1.f / tot;

    for (int k = tid; k < n; k += 256)        R[k] = buf[k] * inv;
    for (int k = n + tid; k < SEQC; k += 256) R[k] = 0.f;
}

// ---------------------------------------------------------------------------
// Context: O[b,q,j] = sum_k P[b,q,k] * Vp[b,k,j]. Tile 64q x 64j, BK=16,
// 256 threads, 4x4 micro. Grid (1, 32, 4). Causal k-skip.
// ---------------------------------------------------------------------------
__global__ __launch_bounds__(256) void ctx_kernel(const float* __restrict__ P,
                                                  const float* __restrict__ Vp,
                                                  float* __restrict__ O)
{
    __shared__ float Ps[16][66];
    __shared__ float Vs[16][64];

    const int b  = blockIdx.z;
    const int q0 = blockIdx.y * 64;
    const float* Pb = P  + (size_t)b * SEQC * SEQC;
    const float* Vb = Vp + (size_t)b * SEQC * DVC;
    float*       Ob = O  + (size_t)b * SEQC * DVC;

    const int tid = threadIdx.x;
    const int ty  = tid >> 4;
    const int tx  = tid & 15;
    const int rb  = ty * 4;
    const int cb  = tx * 4;

    float acc[4][4];
#pragma unroll
    for (int i = 0; i < 4; i++)
#pragma unroll
        for (int j = 0; j < 4; j++) acc[i][j] = 0.f;

    const int kmax = (q0 + 64 < SEQC) ? (q0 + 64) : SEQC;
    for (int k0 = 0; k0 < kmax; k0 += 16) {
        {
            const int r  = tid >> 2;
            const int f4 = tid & 3;
            float4 v = *(const float4*)(Pb + (size_t)(q0 + r) * SEQC + k0 + f4 * 4);
            Ps[f4 * 4 + 0][r] = v.x; Ps[f4 * 4 + 1][r] = v.y;
            Ps[f4 * 4 + 2][r] = v.z; Ps[f4 * 4 + 3][r] = v.w;
        }
        {
            const int r  = tid >> 4;
            const int f4 = tid & 15;
            float4 v = *(const float4*)(Vb + (size_t)(k0 + r) * DVC + f4 * 4);
            *(float4*)&Vs[r][f4 * 4] = v;
        }
        __syncthreads();

#pragma unroll
        for (int k = 0; k < 16; k++) {
            float a[4], bb[4];
#pragma unroll
            for (int i = 0; i < 4; i++) a[i] = Ps[k][rb + i];
#pragma unroll
            for (int j = 0; j < 4; j++) bb[j] = Vs[k][cb + j];
#pragma unroll
            for (int i = 0; i < 4; i++)
#pragma unroll
                for (int j = 0; j < 4; j++) acc[i][j] = fmaf(a[i], bb[j], acc[i][j]);
        }
        __syncthreads();
    }

#pragma unroll
    for (int i = 0; i < 4; i++)
#pragma unroll
        for (int j = 0; j < 4; j++)
            Ob[(size_t)(q0 + rb + i) * DVC + cb + j] = acc[i][j];
}

// ---------------------------------------------------------------------------
extern "C" void kernel_launch(void* const* d_in, const int* in_sizes, int n_in,
                              void* d_out, int out_size)
{
    const float* X  = (const float*)d_in[0];
    const float* Wq = (const float*)d_in[1];
    const float* Wk = (const float*)d_in[2];
    const float* Wv = (const float*)d_in[3];
    const float* Wo = (const float*)d_in[4];
    float* out = (float*)d_out;

    void *pXh, *pXl, *pWqh, *pWql, *pWkh, *pWkl, *pQh, *pQl, *pKh, *pKl;
    void *pWvo, *pWvoh, *pWvol, *pVp, *pS;
    cudaGetSymbolAddress(&pXh,  g_Xh);   cudaGetSymbolAddress(&pXl,  g_Xl);
    cudaGetSymbolAddress(&pWqh, g_Wqh);  cudaGetSymbolAddress(&pWql, g_Wql);
    cudaGetSymbolAddress(&pWkh, g_Wkh);  cudaGetSymbolAddress(&pWkl, g_Wkl);
    cudaGetSymbolAddress(&pQh,  g_Qh);   cudaGetSymbolAddress(&pQl,  g_Ql);
    cudaGetSymbolAddress(&pKh,  g_Kh);   cudaGetSymbolAddress(&pKl,  g_Kl);
    cudaGetSymbolAddress(&pWvo, g_Wvo);
    cudaGetSymbolAddress(&pWvoh, g_Wvoh); cudaGetSymbolAddress(&pWvol, g_Wvol);
    cudaGetSymbolAddress(&pVp,  g_Vp);   cudaGetSymbolAddress(&pS,   g_S);

    cudaFuncSetAttribute(gemm_proj,   cudaFuncAttributeMaxDynamicSharedMemorySize, SMEM_TOT(128));
    cudaFuncSetAttribute(gemm_scores, cudaFuncAttributeMaxDynamicSharedMemorySize, SMEM_TOT(128));
    cudaFuncSetAttribute(gemm_vp,     cudaFuncAttributeMaxDynamicSharedMemorySize, SMEM_TOT(64));

    // Split inputs into bf16 hi/lo
    cvt_pair<<<MTOT * D_MODELC / 4 / 256, 256>>>((const float4*)X,  (uint32_t*)pXh,  (uint32_t*)pXl,  MTOT * D_MODELC / 4);
    cvt_pair<<<D_MODELC * D_MODELC / 4 / 256, 256>>>((const float4*)Wq, (uint32_t*)pWqh, (uint32_t*)pWql, D_MODELC * D_MODELC / 4);
    cvt_pair<<<D_MODELC * D_MODELC / 4 / 256, 256>>>((const float4*)Wk, (uint32_t*)pWkh, (uint32_t*)pWkl, D_MODELC * D_MODELC / 4);

    // Wvo = Wo @ Wv (fp32), then split
    wvo_kernel<<<256, 256>>>(Wo, Wv, (float*)pWvo);
    cvt_pair<<<DVC * D_MODELC / 4 / 256, 256>>>((const float4*)pWvo, (uint32_t*)pWvoh, (uint32_t*)pWvol, DVC * D_MODELC / 4);

    // Q/K projections (tensor path via mma.sync), outputs bf16 hi/lo
    gemm_proj<<<dim3(8, 64), 256, SMEM_TOT(128)>>>(
        (const uint4*)pXh, (const uint4*)pXl, (const uint4*)pWqh, (const uint4*)pWql,
        (uint32_t*)pQh, (uint32_t*)pQl);
    gemm_proj<<<dim3(8, 64), 256, SMEM_TOT(128)>>>(
        (const uint4*)pXh, (const uint4*)pXl, (const uint4*)pWkh, (const uint4*)pWkl,
        (uint32_t*)pKh, (uint32_t*)pKl);

    // V' = X @ Wvo^T (tensor path), fp32 out
    gemm_vp<<<dim3(1, 64), 256, SMEM_TOT(64)>>>(
        (const uint4*)pXh, (const uint4*)pXl, (const uint4*)pWvoh, (const uint4*)pWvol,
        (float*)pVp);

    // Causal scores (tensor path)
    gemm_scores<<<dim3(16, 16, 4), 256, SMEM_TOT(128)>>>(
        (const uint4*)pQh, (const uint4*)pQl, (const uint4*)pKh, (const uint4*)pKl,
        (float*)pS);

    // Softmax rows (in place)
    softmax_kernel<<<MTOT, 256>>>((float*)pS);

    // out = attn @ V'
    ctx_kernel<<<dim3(1, 32, 4), 256>>>((const float*)pS, (const float*)pVp, out);
}

// round 17
// speedup vs baseline: 2.3600x; 1.0382x over previous
#include <cuda_runtime.h>
#include <cuda_bf16.h>
#include <cstdint>
#include <cstddef>

#define D_MODELC 1024
#define SEQC     2048
#define BATCHC   4
#define DVC      64
#define MTOT     (BATCHC * SEQC)   // 8192

// ---------------------------------------------------------------------------
// Scratch (__device__ globals; no allocations allowed)
// ---------------------------------------------------------------------------
__device__ __align__(256) uint32_t g_Xh[MTOT * D_MODELC / 2];
__device__ __align__(256) uint32_t g_Xl[MTOT * D_MODELC / 2];
__device__ __align__(256) uint32_t g_Wqh[D_MODELC * D_MODELC / 2];
__device__ __align__(256) uint32_t g_Wql[D_MODELC * D_MODELC / 2];
__device__ __align__(256) uint32_t g_Wkh[D_MODELC * D_MODELC / 2];
__device__ __align__(256) uint32_t g_Wkl[D_MODELC * D_MODELC / 2];
__device__ __align__(256) uint32_t g_Qh[MTOT * D_MODELC / 2];
__device__ __align__(256) uint32_t g_Ql[MTOT * D_MODELC / 2];
__device__ __align__(256) uint32_t g_Kh[MTOT * D_MODELC / 2];
__device__ __align__(256) uint32_t g_Kl[MTOT * D_MODELC / 2];
__device__ __align__(256) float    g_Wvo[DVC * D_MODELC];
__device__ __align__(256) uint32_t g_Wvoh[DVC * D_MODELC / 2];
__device__ __align__(256) uint32_t g_Wvol[DVC * D_MODELC / 2];
__device__ __align__(256) float    g_Vp[MTOT * DVC];
__device__ __align__(256) float    g_S[BATCHC * SEQC * SEQC];

// ---------------------------------------------------------------------------
// Helpers
// ---------------------------------------------------------------------------
__device__ __forceinline__ uint32_t smem_u32(const void* p) {
    uint32_t a;
    asm("{ .reg .u64 t; cvta.to.shared.u64 t, %1; cvt.u32.u64 %0, t; }"
        : "=r"(a) : "l"(p));
    return a;
}

__device__ __forceinline__ void cp_async16(uint32_t dst, const void* src) {
    asm volatile("cp.async.cg.shared.global [%0], [%1], 16;" :: "r"(dst), "l"(src));
}
__device__ __forceinline__ void cp_commit() {
    asm volatile("cp.async.commit_group;" ::: "memory");
}
__device__ __forceinline__ void cp_wait0() {
    asm volatile("cp.async.wait_group 0;" ::: "memory");
}
__device__ __forceinline__ void cp_wait1() {
    asm volatile("cp.async.wait_group 1;" ::: "memory");
}
__device__ __forceinline__ void cp_wait2() {
    asm volatile("cp.async.wait_group 2;" ::: "memory");
}

// bf16 mma.sync m16n8k16, fp32 accumulate (sm_80+ PTX; legal at compute_103)
__device__ __forceinline__ void mma16816(float* c, const uint32_t* a, const uint32_t* b) {
    asm volatile(
        "mma.sync.aligned.m16n8k16.row.col.f32.bf16.bf16.f32 "
        "{%0,%1,%2,%3}, {%4,%5,%6,%7}, {%8,%9}, {%0,%1,%2,%3};"
        : "+f"(c[0]), "+f"(c[1]), "+f"(c[2]), "+f"(c[3])
        : "r"(a[0]), "r"(a[1]), "r"(a[2]), "r"(a[3]), "r"(b[0]), "r"(b[1]));
}

// ldmatrix x4: four 8x8 b16 tiles, lane i of each 8-lane group supplies row addr
__device__ __forceinline__ void ldsm4(uint32_t* r, uint32_t addr) {
    asm volatile("ldmatrix.sync.aligned.m8n8.x4.shared.b16 {%0,%1,%2,%3}, [%4];"
        : "=r"(r[0]), "=r"(r[1]), "=r"(r[2]), "=r"(r[3]) : "r"(addr));
}

// ---------------------------------------------------------------------------
// Shared bf16-split mainloop (mma.sync): acc += Ah@Bh^T + Ah@Bl^T + Al@Bh^T
// A tile: 128 rows, B tile: BN rows, both K-major bf16, gmem row = 128 uint4
// (1024 bf16). BK=32, 32 chunks (K=1024). 512 threads, 16 warps 4x4,
// warp tile 32 x (BN/4). Smem rows padded to 80B: conflict-free, 16B-aligned.
// 3-stage cp.async pipeline; ldmatrix.x4 fragment loads.
// ---------------------------------------------------------------------------
#define GEMM_THREADS 512
#define LDSM 20                       // u32 per smem row (80B)
#define A_TILE_B 10240                // 128*80
#define STAGE_B(BN) (2 * A_TILE_B + 2 * (BN) * 80)
#define SMEM_TOT(BN) (3 * STAGE_B(BN))

template <int BN>
__device__ __forceinline__ void mainloop_mma(
    const uint4* __restrict__ Ah, const uint4* __restrict__ Al,
    const uint4* __restrict__ Bh, const uint4* __restrict__ Bl,
    float (*acc)[BN / 32][4])
{
    extern __shared__ char smch[];
    const uint32_t smb = smem_u32(smch);
    constexpr int WN    = BN / 4;        // warp n-extent (32 or 16)
    constexpr int NI    = WN / 8;        // n-fragments per warp (4 or 2)
    constexpr int STAGE = STAGE_B(BN);
    constexpr int BSEGS = 2 * BN * 4;    // 16B segments for both B tiles
    constexpr int BPER  = (BSEGS + GEMM_THREADS - 1) / GEMM_THREADS;

    const int tid  = threadIdx.x;
    const int lane = tid & 31;
    const int wid  = tid >> 5;           // 0..15
    const int wm0  = (wid & 3) * 32;
    const int wn0  = (wid >> 2) * WN;

    // ldmatrix lane-address offsets (bytes within a tile)
    // A (16x16): mat0 = m-lo/k-lo, mat1 = m-hi/k-lo, mat2 = m-lo/k-hi, mat3 = m-hi/k-hi
    const int a_off = (wm0 + ((lane >> 3) & 1) * 8 + (lane & 7)) * 80 + (lane >> 4) * 16;
    // B (2x n8k16): mat0 = ni0/k-lo, mat1 = ni0/k-hi, mat2 = ni1/k-lo, mat3 = ni1/k-hi
    const int b_off = (wn0 + (lane >> 4) * 8 + (lane & 7)) * 80 + ((lane >> 3) & 1) * 16;

#pragma unroll
    for (int mi = 0; mi < 2; mi++)
#pragma unroll
        for (int ni = 0; ni < NI; ni++)
#pragma unroll
            for (int v = 0; v < 4; v++) acc[mi][ni][v] = 0.f;

    // ---- prefetch chunk c into stage s ----
    auto prefetch = [&](int c, int s) {
        const uint32_t base = smb + s * STAGE;
        // A tiles (Ah, Al): 2 * 128 rows * 4 segs = 1024 segs
#pragma unroll
        for (int i = 0; i < 2; i++) {
            int idx  = i * GEMM_THREADS + tid;   // 0..1023
            int tile = idx >> 9;                 // 0 = Ah, 1 = Al
            int rem  = idx & 511;
            int r    = rem >> 2;
            int seg  = rem & 3;
            const uint4* src = (tile ? Al : Ah) + (size_t)r * 128 + c * 4 + seg;
            cp_async16(base + tile * A_TILE_B + r * 80 + seg * 16, src);
        }
        // B tiles (Bh, Bl): 2 * BN rows * 4 segs
#pragma unroll
        for (int i = 0; i < BPER; i++) {
            int idx  = i * GEMM_THREADS + tid;
            if (BSEGS < GEMM_THREADS && idx >= BSEGS) break;
            int tile = idx / (BN * 4);
            int rem  = idx % (BN * 4);
            int r    = rem >> 2;
            int seg  = rem & 3;
            const uint4* src = (tile ? Bl : Bh) + (size_t)r * 128 + c * 4 + seg;
            cp_async16(base + 2 * A_TILE_B + tile * (BN * 80) + r * 80 + seg * 16, src);
        }
        cp_commit();
    };

    prefetch(0, 0);
    prefetch(1, 1);

    for (int c = 0; c < 32; c++) {
        const int s = c - (c / 3) * 3;    // c % 3
        if (c + 2 < 32) {
            prefetch(c + 2, (c + 2) % 3);
            cp_wait2();
        } else if (c + 1 < 32) {
            cp_wait1();
        } else {
            cp_wait0();
        }
        __syncthreads();

        const uint32_t Ahb = smb + s * STAGE;
        const uint32_t Alb = Ahb + A_TILE_B;
        const uint32_t Bhb = Ahb + 2 * A_TILE_B;
        const uint32_t Blb = Bhb + BN * 80;

#pragma unroll
        for (int ks = 0; ks < 2; ks++) {
            const int koff = ks * 32;
            uint32_t ah[2][4], al[2][4], bh[NI][2], bl[NI][2];
#pragma unroll
            for (int mi = 0; mi < 2; mi++) {
                ldsm4(ah[mi], Ahb + a_off + mi * 1280 + koff);
                ldsm4(al[mi], Alb + a_off + mi * 1280 + koff);
            }
#pragma unroll
            for (int p = 0; p < NI / 2; p++) {
                ldsm4(&bh[2 * p][0], Bhb + b_off + p * 1280 + koff);
                ldsm4(&bl[2 * p][0], Blb + b_off + p * 1280 + koff);
            }
#pragma unroll
            for (int mi = 0; mi < 2; mi++)
#pragma unroll
                for (int ni = 0; ni < NI; ni++) {
                    mma16816(acc[mi][ni], ah[mi], bh[ni]);
                    mma16816(acc[mi][ni], ah[mi], bl[ni]);
                    mma16816(acc[mi][ni], al[mi], bh[ni]);
                }
        }
        __syncthreads();
    }
}

// ---------------------------------------------------------------------------
// Projection GEMM: C = A @ B^T, output packed bf16 hi/lo. Grid (N/128, M/128).
// ---------------------------------------------------------------------------
__global__ __launch_bounds__(GEMM_THREADS, 1) void gemm_proj(
    const uint4* __restrict__ Ah, const uint4* __restrict__ Al,
    const uint4* __restrict__ Bh, const uint4* __restrict__ Bl,
    uint32_t* __restrict__ Ch, uint32_t* __restrict__ Cl)
{
    const int m0 = blockIdx.y * 128;
    const int n0 = blockIdx.x * 128;
    const int ldU = D_MODELC / 8;

    float acc[2][4][4];
    mainloop_mma<128>(Ah + (size_t)m0 * ldU, Al + (size_t)m0 * ldU,
                      Bh + (size_t)n0 * ldU, Bl + (size_t)n0 * ldU, acc);

    const int lane = threadIdx.x & 31, wid = threadIdx.x >> 5;
    const int g = lane >> 2, tg = lane & 3;
    const int wm0 = (wid & 3) * 32, wn0 = (wid >> 2) * 32;

#pragma unroll
    for (int mi = 0; mi < 2; mi++)
#pragma unroll
        for (int ni = 0; ni < 4; ni++) {
            const int col = n0 + wn0 + ni * 8 + tg * 2;
#pragma unroll
            for (int h = 0; h < 2; h++) {   // h=0: rows g, h=1: rows g+8
                const int row = m0 + wm0 + mi * 16 + g + h * 8;
                const float v0 = acc[mi][ni][h * 2 + 0];
                const float v1 = acc[mi][ni][h * 2 + 1];
                __nv_bfloat16 h0 = __float2bfloat16(v0);
                __nv_bfloat16 h1 = __float2bfloat16(v1);
                __nv_bfloat16 l0 = __float2bfloat16(v0 - __bfloat162float(h0));
                __nv_bfloat16 l1 = __float2bfloat16(v1 - __bfloat162float(h1));
                const size_t idx = ((size_t)row * D_MODELC + col) / 2;
                Ch[idx] = (uint32_t)__bfloat16_as_ushort(h0) |
                          ((uint32_t)__bfloat16_as_ushort(h1) << 16);
                Cl[idx] = (uint32_t)__bfloat16_as_ushort(l0) |
                          ((uint32_t)__bfloat16_as_ushort(l1) << 16);
            }
        }
}

// ---------------------------------------------------------------------------
// Causal scores: S[b,q,k] = (Q·K)/32 for k<=q, 0 for k>q (zeros only arise in
// diagonal tiles; off-diagonal kept tiles always have col<q). Grid (16,16,4).
// ---------------------------------------------------------------------------
__global__ __launch_bounds__(GEMM_THREADS, 1) void gemm_scores(
    const uint4* __restrict__ Qh, const uint4* __restrict__ Ql,
    const uint4* __restrict__ Kh, const uint4* __restrict__ Kl,
    float* __restrict__ S)
{
    if (blockIdx.x > blockIdx.y) return;
    const int b  = blockIdx.z;
    const int m0 = blockIdx.y * 128;
    const int n0 = blockIdx.x * 128;
    const int ldU = D_MODELC / 8;
    const size_t boff = (size_t)b * SEQC * ldU;

    float acc[2][4][4];
    mainloop_mma<128>(Qh + boff + (size_t)m0 * ldU, Ql + boff + (size_t)m0 * ldU,
                      Kh + boff + (size_t)n0 * ldU, Kl + boff + (size_t)n0 * ldU, acc);

    const int lane = threadIdx.x & 31, wid = threadIdx.x >> 5;
    const int g = lane >> 2, tg = lane & 3;
    const int wm0 = (wid & 3) * 32, wn0 = (wid >> 2) * 32;
    float* Sb = S + (size_t)b * SEQC * SEQC;

#pragma unroll
    for (int mi = 0; mi < 2; mi++)
#pragma unroll
        for (int ni = 0; ni < 4; ni++) {
            const int col = n0 + wn0 + ni * 8 + tg * 2;
#pragma unroll
            for (int h = 0; h < 2; h++) {
                const int q = m0 + wm0 + mi * 16 + g + h * 8;
                float* R = Sb + (size_t)q * SEQC;
                R[col]     = (col     <= q) ? acc[mi][ni][h * 2 + 0] * 0.03125f : 0.f;
                R[col + 1] = (col + 1 <= q) ? acc[mi][ni][h * 2 + 1] * 0.03125f : 0.f;
            }
        }
}

// ---------------------------------------------------------------------------
// V' GEMM: Vp = X @ Wvo^T  [8192,64] fp32. BN=64, grid (1,64).
// ---------------------------------------------------------------------------
__global__ __launch_bounds__(GEMM_THREADS, 1) void gemm_vp(
    const uint4* __restrict__ Ah, const uint4* __restrict__ Al,
    const uint4* __restrict__ Bh, const uint4* __restrict__ Bl,
    float* __restrict__ Vp)
{
    const int m0 = blockIdx.y * 128;
    const int ldU = D_MODELC / 8;

    float acc[2][2][4];
    mainloop_mma<64>(Ah + (size_t)m0 * ldU, Al + (size_t)m0 * ldU, Bh, Bl, acc);

    const int lane = threadIdx.x & 31, wid = threadIdx.x >> 5;
    const int g = lane >> 2, tg = lane & 3;
    const int wm0 = (wid & 3) * 32, wn0 = (wid >> 2) * 16;

#pragma unroll
    for (int mi = 0; mi < 2; mi++)
#pragma unroll
        for (int ni = 0; ni < 2; ni++) {
            const int col = wn0 + ni * 8 + tg * 2;
#pragma unroll
            for (int h = 0; h < 2; h++) {
                const int row = m0 + wm0 + mi * 16 + g + h * 8;
                Vp[(size_t)row * DVC + col]     = acc[mi][ni][h * 2 + 0];
                Vp[(size_t)row * DVC + col + 1] = acc[mi][ni][h * 2 + 1];
            }
        }
}

// ---------------------------------------------------------------------------
// fp32 -> bf16 hi/lo split (packed pairs). One float4 per thread.
// ---------------------------------------------------------------------------
__global__ __launch_bounds__(256) void cvt_pair(const float4* __restrict__ in,
                                                uint32_t* __restrict__ hi,
                                                uint32_t* __restrict__ lo, int n4)
{
    int i = blockIdx.x * blockDim.x + threadIdx.x;
    if (i >= n4) return;
    float4 v = in[i];
    __nv_bfloat16 h0 = __float2bfloat16(v.x), h1 = __float2bfloat16(v.y);
    __nv_bfloat16 h2 = __float2bfloat16(v.z), h3 = __float2bfloat16(v.w);
    __nv_bfloat16 l0 = __float2bfloat16(v.x - __bfloat162float(h0));
    __nv_bfloat16 l1 = __float2bfloat16(v.y - __bfloat162float(h1));
    __nv_bfloat16 l2 = __float2bfloat16(v.z - __bfloat162float(h2));
    __nv_bfloat16 l3 = __float2bfloat16(v.w - __bfloat162float(h3));
    hi[2 * i]     = (uint32_t)__bfloat16_as_ushort(h0) | ((uint32_t)__bfloat16_as_ushort(h1) << 16);
    hi[2 * i + 1] = (uint32_t)__bfloat16_as_ushort(h2) | ((uint32_t)__bfloat16_as_ushort(h3) << 16);
    lo[2 * i]     = (uint32_t)__bfloat16_as_ushort(l0) | ((uint32_t)__bfloat16_as_ushort(l1) << 16);
    lo[2 * i + 1] = (uint32_t)__bfloat16_as_ushort(l2) | ((uint32_t)__bfloat16_as_ushort(l3) << 16);
}

// ---------------------------------------------------------------------------
// Wvo = Wo @ Wv (64 x 1024), fp32, split-K over 4 e-chunks with atomicAdd.
// ---------------------------------------------------------------------------
__global__ __launch_bounds__(256) void zero_wvo(float* __restrict__ W)
{
    W[blockIdx.x * 256 + threadIdx.x] = 0.f;
}

__global__ __launch_bounds__(256) void wvo_kernel(const float* __restrict__ Wo,
                                                  const float* __restrict__ Wv,
                                                  float* __restrict__ Wvo)
{
    const int idx = blockIdx.x * 256 + threadIdx.x;   // 0..65535
    const int e0  = blockIdx.y * 256;                 // K chunk
    const int j = idx >> 10;
    const int d = idx & 1023;
    const float* wo = Wo + (size_t)j * D_MODELC + e0;
    const float* wv = Wv + (size_t)e0 * D_MODELC + d;

    float s0 = 0.f, s1 = 0.f, s2 = 0.f, s3 = 0.f;
#pragma unroll 4
    for (int e = 0; e < 256; e += 4) {
        s0 = fmaf(__ldg(wo + e + 0), __ldg(wv + (size_t)(e + 0) * D_MODELC), s0);
        s1 = fmaf(__ldg(wo + e + 1), __ldg(wv + (size_t)(e + 1) * D_MODELC), s1);
        s2 = fmaf(__ldg(wo + e + 2), __ldg(wv + (size_t)(e + 2) * D_MODELC), s2);
        s3 = fmaf(__ldg(wo + e + 3), __ldg(wv + (size_t)(e + 3) * D_MODELC), s3);
    }
    atomicAdd(&Wvo[idx], (s0 + s1) + (s2 + s3));
}

// ---------------------------------------------------------------------------
// Row softmax over valid prefix [0, q]. k>q already zero (written by scores).
// One block per row; warp-shuffle reductions.
// ---------------------------------------------------------------------------
__global__ __launch_bounds__(256) void softmax_kernel(float* __restrict__ S)
{
    __shared__ float buf[SEQC];
    __shared__ float red[8];

    const int row = blockIdx.x;
    const int b   = row / SEQC;
    const int q   = row % SEQC;
    float* R = S + (size_t)b * SEQC * SEQC + (size_t)q * SEQC;
    const int n   = q + 1;
    const int tid = threadIdx.x;
    const int lane = tid & 31, wrp = tid >> 5;

    float lmax = -1e30f;
    for (int k = tid; k < n; k += 256) {
        float v = R[k];
        buf[k] = v;
        lmax = fmaxf(lmax, v);
    }
#pragma unroll
    for (int o = 16; o > 0; o >>= 1)
        lmax = fmaxf(lmax, __shfl_xor_sync(0xffffffffu, lmax, o));
    if (lane == 0) red[wrp] = lmax;
    __syncthreads();
    float m = red[lane & 7];
#pragma unroll
    for (int o = 4; o > 0; o >>= 1)
        m = fmaxf(m, __shfl_xor_sync(0xffffffffu, m, o));

    float lsum = 0.f;
    for (int k = tid; k < n; k += 256) {
        float e = __expf(buf[k] - m);
        buf[k] = e;
        lsum += e;
    }
#pragma unroll
    for (int o = 16; o > 0; o >>= 1)
        lsum += __shfl_xor_sync(0xffffffffu, lsum, o);
    if (lane == 0) red[wrp] = lsum;
    __syncthreads();
    float tot = red[lane & 7];
#pragma unroll
    for (int o = 4; o > 0; o >>= 1)
        tot += __shfl_xor_sync(0xffffffffu, tot, o);
    const float inv = 1.f / tot;

    for (int k = tid; k < n; k += 256) R[k] = buf[k] * inv;
}

// ---------------------------------------------------------------------------
// Context: O[b,q,j] = sum_k P[b,q,k] * Vp[b,k,j]. Tile 64q x 64j, BK=16,
// 256 threads, 4x4 micro. Grid (1, 32, 4). Causal k-skip.
// ---------------------------------------------------------------------------
__global__ __launch_bounds__(256) void ctx_kernel(const float* __restrict__ P,
                                                  const float* __restrict__ Vp,
                                                  float* __restrict__ O)
{
    __shared__ float Ps[16][66];
    __shared__ float Vs[16][64];

    const int b  = blockIdx.z;
    const int q0 = blockIdx.y * 64;
    const float* Pb = P  + (size_t)b * SEQC * SEQC;
    const float* Vb = Vp + (size_t)b * SEQC * DVC;
    float*       Ob = O  + (size_t)b * SEQC * DVC;

    const int tid = threadIdx.x;
    const int ty  = tid >> 4;
    const int tx  = tid & 15;
    const int rb  = ty * 4;
    const int cb  = tx * 4;

    float acc[4][4];
#pragma unroll
    for (int i = 0; i < 4; i++)
#pragma unroll
        for (int j = 0; j < 4; j++) acc[i][j] = 0.f;

    const int kmax = (q0 + 64 < SEQC) ? (q0 + 64) : SEQC;
    for (int k0 = 0; k0 < kmax; k0 += 16) {
        {
            const int r  = tid >> 2;
            const int f4 = tid & 3;
            float4 v = *(const float4*)(Pb + (size_t)(q0 + r) * SEQC + k0 + f4 * 4);
            Ps[f4 * 4 + 0][r] = v.x; Ps[f4 * 4 + 1][r] = v.y;
            Ps[f4 * 4 + 2][r] = v.z; Ps[f4 * 4 + 3][r] = v.w;
        }
        {
            const int r  = tid >> 4;
            const int f4 = tid & 15;
            float4 v = *(const float4*)(Vb + (size_t)(k0 + r) * DVC + f4 * 4);
            *(float4*)&Vs[r][f4 * 4] = v;
        }
        __syncthreads();

#pragma unroll
        for (int k = 0; k < 16; k++) {
            float a[4], bb[4];
#pragma unroll
            for (int i = 0; i < 4; i++) a[i] = Ps[k][rb + i];
#pragma unroll
            for (int j = 0; j < 4; j++) bb[j] = Vs[k][cb + j];
#pragma unroll
            for (int i = 0; i < 4; i++)
#pragma unroll
                for (int j = 0; j < 4; j++) acc[i][j] = fmaf(a[i], bb[j], acc[i][j]);
        }
        __syncthreads();
    }

#pragma unroll
    for (int i = 0; i < 4; i++)
#pragma unroll
        for (int j = 0; j < 4; j++)
            Ob[(size_t)(q0 + rb + i) * DVC + cb + j] = acc[i][j];
}

// ---------------------------------------------------------------------------
extern "C" void kernel_launch(void* const* d_in, const int* in_sizes, int n_in,
                              void* d_out, int out_size)
{
    const float* X  = (const float*)d_in[0];
    const float* Wq = (const float*)d_in[1];
    const float* Wk = (const float*)d_in[2];
    const float* Wv = (const float*)d_in[3];
    const float* Wo = (const float*)d_in[4];
    float* out = (float*)d_out;

    void *pXh, *pXl, *pWqh, *pWql, *pWkh, *pWkl, *pQh, *pQl, *pKh, *pKl;
    void *pWvo, *pWvoh, *pWvol, *pVp, *pS;
    cudaGetSymbolAddress(&pXh,  g_Xh);   cudaGetSymbolAddress(&pXl,  g_Xl);
    cudaGetSymbolAddress(&pWqh, g_Wqh);  cudaGetSymbolAddress(&pWql, g_Wql);
    cudaGetSymbolAddress(&pWkh, g_Wkh);  cudaGetSymbolAddress(&pWkl, g_Wkl);
    cudaGetSymbolAddress(&pQh,  g_Qh);   cudaGetSymbolAddress(&pQl,  g_Ql);
    cudaGetSymbolAddress(&pKh,  g_Kh);   cudaGetSymbolAddress(&pKl,  g_Kl);
    cudaGetSymbolAddress(&pWvo, g_Wvo);
    cudaGetSymbolAddress(&pWvoh, g_Wvoh); cudaGetSymbolAddress(&pWvol, g_Wvol);
    cudaGetSymbolAddress(&pVp,  g_Vp);   cudaGetSymbolAddress(&pS,   g_S);

    cudaFuncSetAttribute(gemm_proj,   cudaFuncAttributeMaxDynamicSharedMemorySize, SMEM_TOT(128));
    cudaFuncSetAttribute(gemm_scores, cudaFuncAttributeMaxDynamicSharedMemorySize, SMEM_TOT(128));
    cudaFuncSetAttribute(gemm_vp,     cudaFuncAttributeMaxDynamicSharedMemorySize, SMEM_TOT(64));

    // Split inputs into bf16 hi/lo
    cvt_pair<<<MTOT * D_MODELC / 4 / 256, 256>>>((const float4*)X,  (uint32_t*)pXh,  (uint32_t*)pXl,  MTOT * D_MODELC / 4);
    cvt_pair<<<D_MODELC * D_MODELC / 4 / 256, 256>>>((const float4*)Wq, (uint32_t*)pWqh, (uint32_t*)pWql, D_MODELC * D_MODELC / 4);
    cvt_pair<<<D_MODELC * D_MODELC / 4 / 256, 256>>>((const float4*)Wk, (uint32_t*)pWkh, (uint32_t*)pWkl, D_MODELC * D_MODELC / 4);

    // Wvo = Wo @ Wv (fp32, split-K + atomics), then split
    zero_wvo<<<DVC * D_MODELC / 256, 256>>>((float*)pWvo);
    wvo_kernel<<<dim3(256, 4), 256>>>(Wo, Wv, (float*)pWvo);
    cvt_pair<<<DVC * D_MODELC / 4 / 256, 256>>>((const float4*)pWvo, (uint32_t*)pWvoh, (uint32_t*)pWvol, DVC * D_MODELC / 4);

    // Q/K projections (tensor path via mma.sync), outputs bf16 hi/lo
    gemm_proj<<<dim3(8, 64), GEMM_THREADS, SMEM_TOT(128)>>>(
        (const uint4*)pXh, (const uint4*)pXl, (const uint4*)pWqh, (const uint4*)pWql,
        (uint32_t*)pQh, (uint32_t*)pQl);
    gemm_proj<<<dim3(8, 64), GEMM_THREADS, SMEM_TOT(128)>>>(
        (const uint4*)pXh, (const uint4*)pXl, (const uint4*)pWkh, (const uint4*)pWkl,
        (uint32_t*)pKh, (uint32_t*)pKl);

    // V' = X @ Wvo^T (tensor path), fp32 out
    gemm_vp<<<dim3(1, 64), GEMM_THREADS, SMEM_TOT(64)>>>(
        (const uint4*)pXh, (const uint4*)pXl, (const uint4*)pWvoh, (const uint4*)pWvol,
        (float*)pVp);

    // Causal scores (tensor path)
    gemm_scores<<<dim3(16, 16, 4), GEMM_THREADS, SMEM_TOT(128)>>>(
        (const uint4*)pQh, (const uint4*)pQl, (const uint4*)pKh, (const uint4*)pKl,
        (float*)pS);

    // Softmax rows (in place)
    softmax_kernel<<<MTOT, 256>>>((float*)pS);

    // out = attn @ V'
    ctx_kernel<<<dim3(1, 32, 4), 256>>>((const float*)pS, (const float*)pVp, out);
}